// round 9
// baseline (speedup 1.0000x reference)
#include <cuda_runtime.h>
#include <cuda_bf16.h>
#include <cstdint>

// ---------------------------------------------------------------------------
// BaselineGNN: 4-layer GCN inference.
//   CSR build -> bf16 tensor-core GEMMs (split-weight hi+lo, full-K single
//   stage, 96KB smem) -> bf16 CSR gather (predicated 8-wide, no serial tail)
//   + BN + relu -> deterministic segmented mean-pool + MLP head
// ---------------------------------------------------------------------------

namespace {
constexpr int NMAX  = 100000;
constexpr int EMAX  = 1600000;
constexpr int HDIM  = 128;
constexpr int GMAX  = 256;
constexpr int LAYERS = 4;
constexpr float EPSV = 1e-5f;
constexpr int GEMM_SMEM = 3 * 128 * 128 * 2;   // 98304 B
}

__device__ __nv_bfloat16 g_hbf [NMAX * HDIM];   // h  (GEMM in / agg out / pool in)
__device__ __nv_bfloat16 g_hwbf[NMAX * HDIM];   // hw (GEMM out / agg in)
__device__ __nv_bfloat16 g_wbf_hi[5 * HDIM * HDIM];
__device__ __nv_bfloat16 g_wbf_lo[5 * HDIM * HDIM];
__device__ int   g_degc[NMAX];
__device__ float g_dinv[NMAX];
__device__ int   g_off[NMAX];
__device__ int   g_cur[NMAX];
__device__ int   g_bsums[128];
__device__ int   g_csr_src[EMAX];
__device__ float g_csr_w[EMAX];
__device__ int   g_gstart[GMAX + 1];

// ---------------------------------------------------------------------------

__global__ void k_zero_deg(int n) {
    int i = blockIdx.x * blockDim.x + threadIdx.x;
    if (i < n) g_degc[i] = 0;
}

__global__ void k_hist(const int* __restrict__ dst, int e) {
    int i = blockIdx.x * blockDim.x + threadIdx.x;
    if (i < e) atomicAdd(&g_degc[dst[i]], 1);
}

__global__ void k_scan1(int n) {
    __shared__ int tmp[1024];
    int gid = blockIdx.x * 1024 + threadIdx.x;
    int v = (gid < n) ? g_degc[gid] : 0;
    if (gid < n) g_dinv[gid] = rsqrtf((float)(v + 1));
    tmp[threadIdx.x] = v;
    __syncthreads();
    for (int d = 1; d < 1024; d <<= 1) {
        int t = (threadIdx.x >= d) ? tmp[threadIdx.x - d] : 0;
        __syncthreads();
        tmp[threadIdx.x] += t;
        __syncthreads();
    }
    if (gid < n) g_off[gid] = tmp[threadIdx.x] - v;   // exclusive
    if (threadIdx.x == 1023) g_bsums[blockIdx.x] = tmp[1023];
}

__global__ void k_scan2(int nb) {
    __shared__ int s[128];
    int tid = threadIdx.x;
    if (tid < nb) s[tid] = g_bsums[tid];
    __syncthreads();
    if (tid == 0) {
        int run = 0;
        for (int i = 0; i < nb; i++) { int t = s[i]; s[i] = run; run += t; }
    }
    __syncthreads();
    if (tid < nb) g_bsums[tid] = s[tid];
}

__global__ void k_scan3(int n) {
    int gid = blockIdx.x * 1024 + threadIdx.x;
    if (gid < n) {
        int v = g_off[gid] + g_bsums[blockIdx.x];
        g_off[gid] = v;
        g_cur[gid] = v;
    }
}

__global__ void k_scatter(const int* __restrict__ src, const int* __restrict__ dst, int e) {
    int i = blockIdx.x * blockDim.x + threadIdx.x;
    if (i < e) {
        int d = dst[i], s = src[i];
        int p = atomicAdd(&g_cur[d], 1);
        g_csr_src[p] = s;
        g_csr_w[p]   = g_dinv[s] * g_dinv[d];
    }
}

__global__ void k_gbound(const int* __restrict__ batch, int n, int G) {
    int i = blockIdx.x * blockDim.x + threadIdx.x;
    if (i >= n) return;
    int bi = batch[i];
    int bp = (i == 0) ? -1 : batch[i - 1];
    for (int g = bp + 1; g <= bi; g++) g_gstart[g] = i;
    if (i == n - 1)
        for (int g = bi + 1; g <= G; g++) g_gstart[g] = n;
}

__global__ void k_cvtW(const float* __restrict__ W_in, const float* __restrict__ Ws) {
    int i = blockIdx.x * blockDim.x + threadIdx.x;
    if (i >= 5 * HDIM * HDIM) return;
    float w = (i < HDIM * HDIM) ? W_in[i] : Ws[i - HDIM * HDIM];
    __nv_bfloat16 hi = __float2bfloat16_rn(w);
    g_wbf_hi[i] = hi;
    g_wbf_lo[i] = __float2bfloat16_rn(w - __bfloat162float(hi));
}

// ---------------------------------------------------------------------------
// Tensor-core GEMM: C[M,128] = A[M,128] @ (W_hi + W_lo)[128,128]
// Full K resident: As 32KB + Bh 32KB + Bl 32KB dynamic smem, single sync.
// ---------------------------------------------------------------------------

__device__ __forceinline__ void ldsm_x4(uint32_t* r, uint32_t addr) {
    asm volatile("ldmatrix.sync.aligned.m8n8.x4.shared.b16 {%0,%1,%2,%3}, [%4];"
        : "=r"(r[0]), "=r"(r[1]), "=r"(r[2]), "=r"(r[3]) : "r"(addr));
}
__device__ __forceinline__ void ldsm_x4_t(uint32_t* r, uint32_t addr) {
    asm volatile("ldmatrix.sync.aligned.m8n8.x4.trans.shared.b16 {%0,%1,%2,%3}, [%4];"
        : "=r"(r[0]), "=r"(r[1]), "=r"(r[2]), "=r"(r[3]) : "r"(addr));
}
__device__ __forceinline__ void mma_bf16(float* c, const uint32_t* a, uint32_t b0, uint32_t b1) {
    asm volatile("mma.sync.aligned.m16n8k16.row.col.f32.bf16.bf16.f32 "
        "{%0,%1,%2,%3}, {%4,%5,%6,%7}, {%8,%9}, {%0,%1,%2,%3};"
        : "+f"(c[0]), "+f"(c[1]), "+f"(c[2]), "+f"(c[3])
        : "r"(a[0]), "r"(a[1]), "r"(a[2]), "r"(a[3]), "r"(b0), "r"(b1));
}

template <int MODE>
__global__ void __launch_bounds__(256)
k_gemm_tc(const float* __restrict__ Afp, int loff,
          const float* __restrict__ bias, int M) {
    extern __shared__ __nv_bfloat16 smem[];
    __nv_bfloat16* As  = smem;
    __nv_bfloat16* Bhs = smem + 128 * 128;
    __nv_bfloat16* Bls = smem + 2 * 128 * 128;
    const __nv_bfloat16* Whi = g_wbf_hi + loff;
    const __nv_bfloat16* Wlo = g_wbf_lo + loff;

    int tid  = threadIdx.x;
    int lane = tid & 31, wid = tid >> 5;
    int wm = wid & 3, wn = wid >> 2;
    int row0 = blockIdx.x * 128;

    uint32_t asb = (uint32_t)__cvta_generic_to_shared(As);
    uint32_t bhb = (uint32_t)__cvta_generic_to_shared(Bhs);
    uint32_t blb = (uint32_t)__cvta_generic_to_shared(Bls);

#pragma unroll
    for (int i = 0; i < 8; i++) {
        int idx = tid + 256 * i;
        int r = idx >> 4, c = idx & 15;
        int gr = row0 + r;
        uint4 u = make_uint4(0u, 0u, 0u, 0u);
        if (gr < M) {
            if (MODE == 0) {
                const float4* p = (const float4*)(Afp + (size_t)gr * 128 + c * 8);
                float4 f0 = p[0], f1 = p[1];
                __nv_bfloat162 h0 = __floats2bfloat162_rn(f0.x, f0.y);
                __nv_bfloat162 h1 = __floats2bfloat162_rn(f0.z, f0.w);
                __nv_bfloat162 h2 = __floats2bfloat162_rn(f1.x, f1.y);
                __nv_bfloat162 h3 = __floats2bfloat162_rn(f1.z, f1.w);
                u.x = *(uint32_t*)&h0; u.y = *(uint32_t*)&h1;
                u.z = *(uint32_t*)&h2; u.w = *(uint32_t*)&h3;
            } else {
                u = *(const uint4*)(g_hbf + (size_t)gr * 128 + c * 8);
            }
        }
        int sw = (c & 8) | ((c & 7) ^ (r & 7));
        *(uint4*)(As + (size_t)(r * 16 + sw) * 8) = u;
    }
#pragma unroll
    for (int i = 0; i < 8; i++) {
        int idx = tid + 256 * i;
        int k = idx >> 4, c = idx & 15;
        int sw = (c & 8) | ((c & 7) ^ (k & 7));
        *(uint4*)(Bhs + (size_t)(k * 16 + sw) * 8) =
            *(const uint4*)(Whi + (size_t)k * 128 + c * 8);
        *(uint4*)(Bls + (size_t)(k * 16 + sw) * 8) =
            *(const uint4*)(Wlo + (size_t)k * 128 + c * 8);
    }
    __syncthreads();

    float acc[2][8][4];
#pragma unroll
    for (int mi = 0; mi < 2; mi++)
#pragma unroll
        for (int nj = 0; nj < 8; nj++)
#pragma unroll
            for (int q = 0; q < 4; q++) acc[mi][nj][q] = 0.f;

#pragma unroll
    for (int ks = 0; ks < 8; ks++) {
        uint32_t a[2][4];
#pragma unroll
        for (int mi = 0; mi < 2; mi++) {
            int r  = wm * 32 + mi * 16 + (lane & 15);
            int ch = ks * 2 + (lane >> 4);
            int sw = (ch & 8) | ((ch & 7) ^ (r & 7));
            ldsm_x4(a[mi], asb + (uint32_t)(r * 16 + sw) * 16);
        }
#pragma unroll
        for (int nj = 0; nj < 4; nj++) {
            int k  = ks * 16 + (lane & 15);
            int ch = wn * 8 + nj * 2 + (lane >> 4);
            int sw = (ch & 8) | ((ch & 7) ^ (k & 7));
            uint32_t bh[4], bl[4];
            ldsm_x4_t(bh, bhb + (uint32_t)(k * 16 + sw) * 16);
            ldsm_x4_t(bl, blb + (uint32_t)(k * 16 + sw) * 16);
#pragma unroll
            for (int mi = 0; mi < 2; mi++) {
                mma_bf16(acc[mi][nj * 2],     a[mi], bh[0], bh[1]);
                mma_bf16(acc[mi][nj * 2 + 1], a[mi], bh[2], bh[3]);
                mma_bf16(acc[mi][nj * 2],     a[mi], bl[0], bl[1]);
                mma_bf16(acc[mi][nj * 2 + 1], a[mi], bl[2], bl[3]);
            }
        }
    }
    int gid = lane >> 2, tig = lane & 3;
    __nv_bfloat16* Out = (MODE == 0) ? g_hbf : g_hwbf;
#pragma unroll
    for (int mi = 0; mi < 2; mi++) {
#pragma unroll
        for (int nj = 0; nj < 8; nj++) {
            int col = wn * 64 + nj * 8 + tig * 2;
            float v0 = acc[mi][nj][0], v1 = acc[mi][nj][1];
            float v2 = acc[mi][nj][2], v3 = acc[mi][nj][3];
            if (MODE == 0) {
                float b0 = bias[col], b1 = bias[col + 1];
                v0 = fmaxf(v0 + b0, 0.f); v1 = fmaxf(v1 + b1, 0.f);
                v2 = fmaxf(v2 + b0, 0.f); v3 = fmaxf(v3 + b1, 0.f);
            }
            int r0 = row0 + wm * 32 + mi * 16 + gid;
            int r1 = r0 + 8;
            if (r0 < M) {
                __nv_bfloat162 p = __floats2bfloat162_rn(v0, v1);
                *(uint32_t*)(Out + (size_t)r0 * 128 + col) = *(uint32_t*)&p;
            }
            if (r1 < M) {
                __nv_bfloat162 p = __floats2bfloat162_rn(v2, v3);
                *(uint32_t*)(Out + (size_t)r1 * 128 + col) = *(uint32_t*)&p;
            }
        }
    }
}

// ---------------------------------------------------------------------------
// bf16 CSR gather + self-loop + bias + BN + relu (fp32 accumulate).
// One warp per node; lane owns 4 features.  Edges processed in predicated
// groups of 8: OOB slots clamp the index to the last edge (L2-hot line) with
// weight 0, so all 8 loads always issue -> MLP=8, no serial tail.
// ---------------------------------------------------------------------------
__device__ __forceinline__ void acc_edge(const __nv_bfloat16* hw, unsigned off,
                                         float wt, float& x, float& y,
                                         float& z, float& w) {
    uint2 u = *(const uint2*)(hw + off);
    float2 a0 = __bfloat1622float2(*(__nv_bfloat162*)&u.x);
    float2 a1 = __bfloat1622float2(*(__nv_bfloat162*)&u.y);
    x += a0.x * wt; y += a0.y * wt; z += a1.x * wt; w += a1.y * wt;
}

__global__ void k_agg(const float* __restrict__ bias,
                      const float* __restrict__ gamma,
                      const float* __restrict__ beta,
                      const float* __restrict__ rmean,
                      const float* __restrict__ rvar,
                      int n, int e) {
    int w    = (blockIdx.x * blockDim.x + threadIdx.x) >> 5;
    int lane = threadIdx.x & 31;
    if (w >= n) return;
    unsigned f = (unsigned)lane * 4;
    const __nv_bfloat16* hw = g_hwbf;

    float dv = g_dinv[w];
    float ws = dv * dv;
    float ax, ay, az, aw;
    {
        uint2 us = *(const uint2*)(hw + ((unsigned)w << 7) + f);
        float2 s0 = __bfloat1622float2(*(__nv_bfloat162*)&us.x);
        float2 s1 = __bfloat1622float2(*(__nv_bfloat162*)&us.y);
        ax = s0.x * ws; ay = s0.y * ws; az = s1.x * ws; aw = s1.y * ws;
    }
    float bx = 0.f, by = 0.f, bz = 0.f, bw = 0.f;

    int j0 = g_off[w];
    int j1 = (w + 1 < n) ? g_off[w + 1] : e;

    if (j0 < j1) {
        int jlast = j1 - 1;
        for (int j = j0; j < j1; j += 8) {
            int   jj[8];
            float wt[8];
            unsigned of[8];
#pragma unroll
            for (int k = 0; k < 8; k++) {
                int t = j + k;
                bool valid = t < j1;
                jj[k] = valid ? t : jlast;
                of[k] = ((unsigned)g_csr_src[jj[k]] << 7) + f;
                wt[k] = valid ? g_csr_w[jj[k]] : 0.f;
            }
            acc_edge(hw, of[0], wt[0], ax, ay, az, aw);
            acc_edge(hw, of[1], wt[1], bx, by, bz, bw);
            acc_edge(hw, of[2], wt[2], ax, ay, az, aw);
            acc_edge(hw, of[3], wt[3], bx, by, bz, bw);
            acc_edge(hw, of[4], wt[4], ax, ay, az, aw);
            acc_edge(hw, of[5], wt[5], bx, by, bz, bw);
            acc_edge(hw, of[6], wt[6], ax, ay, az, aw);
            acc_edge(hw, of[7], wt[7], bx, by, bz, bw);
        }
        ax += bx; ay += by; az += bz; aw += bw;
    }

    float4 bb = *(const float4*)(bias  + f);
    float4 gm = *(const float4*)(gamma + f);
    float4 bt = *(const float4*)(beta  + f);
    float4 rm = *(const float4*)(rmean + f);
    float4 rv = *(const float4*)(rvar  + f);
    float4 o;
    o.x = fmaxf((ax + bb.x - rm.x) * rsqrtf(rv.x + EPSV) * gm.x + bt.x, 0.f);
    o.y = fmaxf((ay + bb.y - rm.y) * rsqrtf(rv.y + EPSV) * gm.y + bt.y, 0.f);
    o.z = fmaxf((az + bb.z - rm.z) * rsqrtf(rv.z + EPSV) * gm.z + bt.z, 0.f);
    o.w = fmaxf((aw + bb.w - rm.w) * rsqrtf(rv.w + EPSV) * gm.w + bt.w, 0.f);
    __nv_bfloat162 q0 = __floats2bfloat162_rn(o.x, o.y);
    __nv_bfloat162 q1 = __floats2bfloat162_rn(o.z, o.w);
    uint2 qo; qo.x = *(uint32_t*)&q0; qo.y = *(uint32_t*)&q1;
    *(uint2*)(g_hbf + ((unsigned)w << 7) + f) = qo;
}

// ---------------------------------------------------------------------------
// Fused segmented mean-pool (bf16 input, fp32 accumulate) + MLP head.
// ---------------------------------------------------------------------------
__global__ void k_poolhead(const float* __restrict__ fc1w, const float* __restrict__ fc1b,
                           const float* __restrict__ fc2w, const float* __restrict__ fc2b,
                           float* __restrict__ out) {
    int g   = blockIdx.x;
    int tid = threadIdx.x;          // 256
    int t    = tid & 127;
    int half = tid >> 7;
    __shared__ float ssum[HDIM];
    __shared__ float ge[HDIM];
    __shared__ float h1[64];

    int s0 = g_gstart[g];
    int s1 = g_gstart[g + 1];
    float acc = 0.f;
#pragma unroll 4
    for (int r = s0 + half; r < s1; r += 2)
        acc += __bfloat162float(g_hbf[(size_t)r * HDIM + t]);
    if (half == 1) ssum[t] = acc;
    __syncthreads();
    if (half == 0) {
        float cnt = fmaxf((float)(s1 - s0), 1.f);
        ge[t] = (acc + ssum[t]) / cnt;
    }
    __syncthreads();

    if (tid < 64) {
        float a = fc1b[tid];
#pragma unroll
        for (int i = 0; i < HDIM; i++) a += ge[i] * fc1w[i * 64 + tid];
        h1[tid] = fmaxf(a, 0.f);
    }
    __syncthreads();
    if (tid < 10) {
        float o = fc2b[tid];
#pragma unroll
        for (int jq = 0; jq < 64; jq++) o += h1[jq] * fc2w[jq * 10 + tid];
        out[g * 10 + tid] = o;
    }
}

// ---------------------------------------------------------------------------

extern "C" void kernel_launch(void* const* d_in, const int* in_sizes, int n_in,
                              void* d_out, int out_size) {
    const float* x      = (const float*)d_in[0];
    const int*   eidx   = (const int*)  d_in[1];
    const int*   batch  = (const int*)  d_in[2];
    const float* W_in   = (const float*)d_in[3];
    const float* b_in   = (const float*)d_in[4];
    const float* Ws     = (const float*)d_in[5];
    const float* bs     = (const float*)d_in[6];
    const float* gammas = (const float*)d_in[7];
    const float* betas  = (const float*)d_in[8];
    const float* rmeans = (const float*)d_in[9];
    const float* rvars  = (const float*)d_in[10];
    const float* fc1w   = (const float*)d_in[11];
    const float* fc1b   = (const float*)d_in[12];
    const float* fc2w   = (const float*)d_in[13];
    const float* fc2b   = (const float*)d_in[14];
    float* out = (float*)d_out;

    int N = in_sizes[2];
    int E = in_sizes[1] / 2;
    int G = out_size / 10;
    const int* src = eidx;
    const int* dst = eidx + E;

    cudaFuncSetAttribute(k_gemm_tc<0>, cudaFuncAttributeMaxDynamicSharedMemorySize, GEMM_SMEM);
    cudaFuncSetAttribute(k_gemm_tc<1>, cudaFuncAttributeMaxDynamicSharedMemorySize, GEMM_SMEM);

    const int TB = 256;
    k_zero_deg<<<(N + TB - 1) / TB, TB>>>(N);
    k_hist<<<(E + TB - 1) / TB, TB>>>(dst, E);
    int nb = (N + 1023) / 1024;
    k_scan1<<<nb, 1024>>>(N);
    k_scan2<<<1, 128>>>(nb);
    k_scan3<<<nb, 1024>>>(N);
    k_scatter<<<(E + TB - 1) / TB, TB>>>(src, dst, E);
    k_gbound<<<(N + TB - 1) / TB, TB>>>(batch, N, G);
    k_cvtW<<<(5 * HDIM * HDIM + TB - 1) / TB, TB>>>(W_in, Ws);

    int gblk = (N + 127) / 128;
    k_gemm_tc<0><<<gblk, 256, GEMM_SMEM>>>(x, 0, b_in, N);
    for (int l = 0; l < LAYERS; l++) {
        k_gemm_tc<1><<<gblk, 256, GEMM_SMEM>>>(nullptr, (1 + l) * HDIM * HDIM, nullptr, N);
        int aggBlocks = (N * 32 + TB - 1) / TB;
        k_agg<<<aggBlocks, TB>>>(bs + l * HDIM, gammas + l * HDIM, betas + l * HDIM,
                                 rmeans + l * HDIM, rvars + l * HDIM, N, E);
    }

    k_poolhead<<<G, 256>>>(fc1w, fc1b, fc2w, fc2b, out);
}

// round 10
// speedup vs baseline: 1.2424x; 1.2424x over previous
#include <cuda_runtime.h>
#include <cuda_bf16.h>
#include <cstdint>

// ---------------------------------------------------------------------------
// BaselineGNN: 4-layer GCN inference.
//   CSR build (self-cleaning degc, merged misc kernel) ->
//   bf16 tensor-core GEMMs (split-weight hi+lo, full-K, 96KB smem) ->
//   bf16 CSR gather (x8 body + scalar tail -- best measured form) ->
//   deterministic segmented mean-pool + widened MLP head
// ---------------------------------------------------------------------------

namespace {
constexpr int NMAX  = 100000;
constexpr int EMAX  = 1600000;
constexpr int HDIM  = 128;
constexpr int GMAX  = 256;
constexpr int LAYERS = 4;
constexpr float EPSV = 1e-5f;
constexpr int GEMM_SMEM = 3 * 128 * 128 * 2;   // 98304 B
}

__device__ __nv_bfloat16 g_hbf [NMAX * HDIM];   // h  (GEMM in / agg out / pool in)
__device__ __nv_bfloat16 g_hwbf[NMAX * HDIM];   // hw (GEMM out / agg in)
__device__ __nv_bfloat16 g_wbf_hi[5 * HDIM * HDIM];
__device__ __nv_bfloat16 g_wbf_lo[5 * HDIM * HDIM];
__device__ int   g_degc[NMAX];                  // zero at entry, re-zeroed by scan1
__device__ float g_dinv[NMAX];
__device__ int   g_off[NMAX];
__device__ int   g_cur[NMAX];
__device__ int   g_bsums[128];
__device__ int   g_csr_src[EMAX];
__device__ float g_csr_w[EMAX];
__device__ int   g_gstart[GMAX + 1];

// ---------------------------------------------------------------------------

__global__ void k_hist(const int* __restrict__ dst, int e) {
    int i = blockIdx.x * blockDim.x + threadIdx.x;
    if (i < e) atomicAdd(&g_degc[dst[i]], 1);
}

// scan1: reads degc, produces dinv + block-local exclusive scan, then zeroes
// degc so the next graph replay starts from a clean histogram.
__global__ void k_scan1(int n) {
    __shared__ int tmp[1024];
    int gid = blockIdx.x * 1024 + threadIdx.x;
    int v = 0;
    if (gid < n) {
        v = g_degc[gid];
        g_degc[gid] = 0;                          // self-clean for next replay
        g_dinv[gid] = rsqrtf((float)(v + 1));
    }
    tmp[threadIdx.x] = v;
    __syncthreads();
    for (int d = 1; d < 1024; d <<= 1) {
        int t = (threadIdx.x >= d) ? tmp[threadIdx.x - d] : 0;
        __syncthreads();
        tmp[threadIdx.x] += t;
        __syncthreads();
    }
    if (gid < n) g_off[gid] = tmp[threadIdx.x] - v;   // exclusive
    if (threadIdx.x == 1023) g_bsums[blockIdx.x] = tmp[1023];
}

// warp-parallel exclusive scan of nb (<=128) block sums
__global__ void k_scan2(int nb) {
    __shared__ float dummy;  (void)dummy;
    __shared__ int s[128];
    int tid = threadIdx.x;
    int v = (tid < nb) ? g_bsums[tid] : 0;
    s[tid] = v;
    __syncthreads();
    for (int d = 1; d < 128; d <<= 1) {
        int t = (tid >= d) ? s[tid - d] : 0;
        __syncthreads();
        s[tid] += t;
        __syncthreads();
    }
    if (tid < nb) g_bsums[tid] = s[tid] - v;      // exclusive
}

__global__ void k_scan3(int n) {
    int gid = blockIdx.x * 1024 + threadIdx.x;
    if (gid < n) {
        int v = g_off[gid] + g_bsums[blockIdx.x];
        g_off[gid] = v;
        g_cur[gid] = v;
    }
}

__global__ void k_scatter(const int* __restrict__ src, const int* __restrict__ dst, int e) {
    int i = blockIdx.x * blockDim.x + threadIdx.x;
    if (i < e) {
        int d = dst[i], s = src[i];
        int p = atomicAdd(&g_cur[d], 1);
        g_csr_src[p] = s;
        g_csr_w[p]   = g_dinv[s] * g_dinv[d];
    }
}

// merged: graph boundaries (blocks [0, gb)) + weight hi/lo conversion (rest)
__global__ void k_misc(const int* __restrict__ batch, int n, int G, int gb,
                       const float* __restrict__ W_in, const float* __restrict__ Ws) {
    int b = blockIdx.x;
    if (b < gb) {
        int i = b * 256 + threadIdx.x;
        if (i >= n) return;
        int bi = batch[i];
        int bp = (i == 0) ? -1 : batch[i - 1];
        for (int g = bp + 1; g <= bi; g++) g_gstart[g] = i;
        if (i == n - 1)
            for (int g = bi + 1; g <= G; g++) g_gstart[g] = n;
    } else {
        int i = (b - gb) * 256 + threadIdx.x;
        if (i >= 5 * HDIM * HDIM) return;
        float w = (i < HDIM * HDIM) ? W_in[i] : Ws[i - HDIM * HDIM];
        __nv_bfloat16 hi = __float2bfloat16_rn(w);
        g_wbf_hi[i] = hi;
        g_wbf_lo[i] = __float2bfloat16_rn(w - __bfloat162float(hi));
    }
}

// ---------------------------------------------------------------------------
// Tensor-core GEMM: C[M,128] = A[M,128] @ (W_hi + W_lo)[128,128]
// Full K resident: As 32KB + Bh 32KB + Bl 32KB dynamic smem, single sync.
// ---------------------------------------------------------------------------

__device__ __forceinline__ void ldsm_x4(uint32_t* r, uint32_t addr) {
    asm volatile("ldmatrix.sync.aligned.m8n8.x4.shared.b16 {%0,%1,%2,%3}, [%4];"
        : "=r"(r[0]), "=r"(r[1]), "=r"(r[2]), "=r"(r[3]) : "r"(addr));
}
__device__ __forceinline__ void ldsm_x4_t(uint32_t* r, uint32_t addr) {
    asm volatile("ldmatrix.sync.aligned.m8n8.x4.trans.shared.b16 {%0,%1,%2,%3}, [%4];"
        : "=r"(r[0]), "=r"(r[1]), "=r"(r[2]), "=r"(r[3]) : "r"(addr));
}
__device__ __forceinline__ void mma_bf16(float* c, const uint32_t* a, uint32_t b0, uint32_t b1) {
    asm volatile("mma.sync.aligned.m16n8k16.row.col.f32.bf16.bf16.f32 "
        "{%0,%1,%2,%3}, {%4,%5,%6,%7}, {%8,%9}, {%0,%1,%2,%3};"
        : "+f"(c[0]), "+f"(c[1]), "+f"(c[2]), "+f"(c[3])
        : "r"(a[0]), "r"(a[1]), "r"(a[2]), "r"(a[3]), "r"(b0), "r"(b1));
}

template <int MODE>
__global__ void __launch_bounds__(256)
k_gemm_tc(const float* __restrict__ Afp, int loff,
          const float* __restrict__ bias, int M) {
    extern __shared__ __nv_bfloat16 smem[];
    __nv_bfloat16* As  = smem;
    __nv_bfloat16* Bhs = smem + 128 * 128;
    __nv_bfloat16* Bls = smem + 2 * 128 * 128;
    const __nv_bfloat16* Whi = g_wbf_hi + loff;
    const __nv_bfloat16* Wlo = g_wbf_lo + loff;

    int tid  = threadIdx.x;
    int lane = tid & 31, wid = tid >> 5;
    int wm = wid & 3, wn = wid >> 2;
    int row0 = blockIdx.x * 128;

    uint32_t asb = (uint32_t)__cvta_generic_to_shared(As);
    uint32_t bhb = (uint32_t)__cvta_generic_to_shared(Bhs);
    uint32_t blb = (uint32_t)__cvta_generic_to_shared(Bls);

#pragma unroll
    for (int i = 0; i < 8; i++) {
        int idx = tid + 256 * i;
        int r = idx >> 4, c = idx & 15;
        int gr = row0 + r;
        uint4 u = make_uint4(0u, 0u, 0u, 0u);
        if (gr < M) {
            if (MODE == 0) {
                const float4* p = (const float4*)(Afp + (size_t)gr * 128 + c * 8);
                float4 f0 = p[0], f1 = p[1];
                __nv_bfloat162 h0 = __floats2bfloat162_rn(f0.x, f0.y);
                __nv_bfloat162 h1 = __floats2bfloat162_rn(f0.z, f0.w);
                __nv_bfloat162 h2 = __floats2bfloat162_rn(f1.x, f1.y);
                __nv_bfloat162 h3 = __floats2bfloat162_rn(f1.z, f1.w);
                u.x = *(uint32_t*)&h0; u.y = *(uint32_t*)&h1;
                u.z = *(uint32_t*)&h2; u.w = *(uint32_t*)&h3;
            } else {
                u = *(const uint4*)(g_hbf + (size_t)gr * 128 + c * 8);
            }
        }
        int sw = (c & 8) | ((c & 7) ^ (r & 7));
        *(uint4*)(As + (size_t)(r * 16 + sw) * 8) = u;
    }
#pragma unroll
    for (int i = 0; i < 8; i++) {
        int idx = tid + 256 * i;
        int k = idx >> 4, c = idx & 15;
        int sw = (c & 8) | ((c & 7) ^ (k & 7));
        *(uint4*)(Bhs + (size_t)(k * 16 + sw) * 8) =
            *(const uint4*)(Whi + (size_t)k * 128 + c * 8);
        *(uint4*)(Bls + (size_t)(k * 16 + sw) * 8) =
            *(const uint4*)(Wlo + (size_t)k * 128 + c * 8);
    }
    __syncthreads();

    float acc[2][8][4];
#pragma unroll
    for (int mi = 0; mi < 2; mi++)
#pragma unroll
        for (int nj = 0; nj < 8; nj++)
#pragma unroll
            for (int q = 0; q < 4; q++) acc[mi][nj][q] = 0.f;

#pragma unroll
    for (int ks = 0; ks < 8; ks++) {
        uint32_t a[2][4];
#pragma unroll
        for (int mi = 0; mi < 2; mi++) {
            int r  = wm * 32 + mi * 16 + (lane & 15);
            int ch = ks * 2 + (lane >> 4);
            int sw = (ch & 8) | ((ch & 7) ^ (r & 7));
            ldsm_x4(a[mi], asb + (uint32_t)(r * 16 + sw) * 16);
        }
#pragma unroll
        for (int nj = 0; nj < 4; nj++) {
            int k  = ks * 16 + (lane & 15);
            int ch = wn * 8 + nj * 2 + (lane >> 4);
            int sw = (ch & 8) | ((ch & 7) ^ (k & 7));
            uint32_t bh[4], bl[4];
            ldsm_x4_t(bh, bhb + (uint32_t)(k * 16 + sw) * 16);
            ldsm_x4_t(bl, blb + (uint32_t)(k * 16 + sw) * 16);
#pragma unroll
            for (int mi = 0; mi < 2; mi++) {
                mma_bf16(acc[mi][nj * 2],     a[mi], bh[0], bh[1]);
                mma_bf16(acc[mi][nj * 2 + 1], a[mi], bh[2], bh[3]);
                mma_bf16(acc[mi][nj * 2],     a[mi], bl[0], bl[1]);
                mma_bf16(acc[mi][nj * 2 + 1], a[mi], bl[2], bl[3]);
            }
        }
    }
    int gid = lane >> 2, tig = lane & 3;
    __nv_bfloat16* Out = (MODE == 0) ? g_hbf : g_hwbf;
#pragma unroll
    for (int mi = 0; mi < 2; mi++) {
#pragma unroll
        for (int nj = 0; nj < 8; nj++) {
            int col = wn * 64 + nj * 8 + tig * 2;
            float v0 = acc[mi][nj][0], v1 = acc[mi][nj][1];
            float v2 = acc[mi][nj][2], v3 = acc[mi][nj][3];
            if (MODE == 0) {
                float b0 = bias[col], b1 = bias[col + 1];
                v0 = fmaxf(v0 + b0, 0.f); v1 = fmaxf(v1 + b1, 0.f);
                v2 = fmaxf(v2 + b0, 0.f); v3 = fmaxf(v3 + b1, 0.f);
            }
            int r0 = row0 + wm * 32 + mi * 16 + gid;
            int r1 = r0 + 8;
            if (r0 < M) {
                __nv_bfloat162 p = __floats2bfloat162_rn(v0, v1);
                *(uint32_t*)(Out + (size_t)r0 * 128 + col) = *(uint32_t*)&p;
            }
            if (r1 < M) {
                __nv_bfloat162 p = __floats2bfloat162_rn(v2, v3);
                *(uint32_t*)(Out + (size_t)r1 * 128 + col) = *(uint32_t*)&p;
            }
        }
    }
}

// ---------------------------------------------------------------------------
// bf16 CSR gather + self-loop + bias + BN + relu (fp32 accumulate).
// One warp per node; lane owns 4 features.  x8 body + scalar tail
// (best measured form -- R9 showed padded/predicated variants regress).
// ---------------------------------------------------------------------------
__device__ __forceinline__ void acc_edge(const __nv_bfloat16* hw, unsigned off,
                                         float wt, float& x, float& y,
                                         float& z, float& w) {
    uint2 u = *(const uint2*)(hw + off);
    float2 a0 = __bfloat1622float2(*(__nv_bfloat162*)&u.x);
    float2 a1 = __bfloat1622float2(*(__nv_bfloat162*)&u.y);
    x += a0.x * wt; y += a0.y * wt; z += a1.x * wt; w += a1.y * wt;
}

__global__ void k_agg(const float* __restrict__ bias,
                      const float* __restrict__ gamma,
                      const float* __restrict__ beta,
                      const float* __restrict__ rmean,
                      const float* __restrict__ rvar,
                      int n, int e) {
    int w    = (blockIdx.x * blockDim.x + threadIdx.x) >> 5;
    int lane = threadIdx.x & 31;
    if (w >= n) return;
    unsigned f = (unsigned)lane * 4;
    const __nv_bfloat16* hw = g_hwbf;

    float dv = g_dinv[w];
    float ws = dv * dv;
    float ax, ay, az, aw;
    {
        uint2 us = *(const uint2*)(hw + ((unsigned)w << 7) + f);
        float2 s0 = __bfloat1622float2(*(__nv_bfloat162*)&us.x);
        float2 s1 = __bfloat1622float2(*(__nv_bfloat162*)&us.y);
        ax = s0.x * ws; ay = s0.y * ws; az = s1.x * ws; aw = s1.y * ws;
    }
    float bx = 0.f, by = 0.f, bz = 0.f, bw = 0.f;

    int j0 = g_off[w];
    int j1 = (w + 1 < n) ? g_off[w + 1] : e;
    int j = j0;
    for (; j + 8 <= j1; j += 8) {
        unsigned o0 = ((unsigned)g_csr_src[j]     << 7) + f; float w0 = g_csr_w[j];
        unsigned o1 = ((unsigned)g_csr_src[j + 1] << 7) + f; float w1 = g_csr_w[j + 1];
        unsigned o2 = ((unsigned)g_csr_src[j + 2] << 7) + f; float w2 = g_csr_w[j + 2];
        unsigned o3 = ((unsigned)g_csr_src[j + 3] << 7) + f; float w3 = g_csr_w[j + 3];
        unsigned o4 = ((unsigned)g_csr_src[j + 4] << 7) + f; float w4 = g_csr_w[j + 4];
        unsigned o5 = ((unsigned)g_csr_src[j + 5] << 7) + f; float w5 = g_csr_w[j + 5];
        unsigned o6 = ((unsigned)g_csr_src[j + 6] << 7) + f; float w6 = g_csr_w[j + 6];
        unsigned o7 = ((unsigned)g_csr_src[j + 7] << 7) + f; float w7 = g_csr_w[j + 7];
        acc_edge(hw, o0, w0, ax, ay, az, aw);
        acc_edge(hw, o1, w1, bx, by, bz, bw);
        acc_edge(hw, o2, w2, ax, ay, az, aw);
        acc_edge(hw, o3, w3, bx, by, bz, bw);
        acc_edge(hw, o4, w4, ax, ay, az, aw);
        acc_edge(hw, o5, w5, bx, by, bz, bw);
        acc_edge(hw, o6, w6, ax, ay, az, aw);
        acc_edge(hw, o7, w7, bx, by, bz, bw);
    }
    for (; j < j1; j++) {
        unsigned o = ((unsigned)g_csr_src[j] << 7) + f;
        acc_edge(hw, o, g_csr_w[j], ax, ay, az, aw);
    }
    ax += bx; ay += by; az += bz; aw += bw;

    float4 bb = *(const float4*)(bias  + f);
    float4 gm = *(const float4*)(gamma + f);
    float4 bt = *(const float4*)(beta  + f);
    float4 rm = *(const float4*)(rmean + f);
    float4 rv = *(const float4*)(rvar  + f);
    float4 o;
    o.x = fmaxf((ax + bb.x - rm.x) * rsqrtf(rv.x + EPSV) * gm.x + bt.x, 0.f);
    o.y = fmaxf((ay + bb.y - rm.y) * rsqrtf(rv.y + EPSV) * gm.y + bt.y, 0.f);
    o.z = fmaxf((az + bb.z - rm.z) * rsqrtf(rv.z + EPSV) * gm.z + bt.z, 0.f);
    o.w = fmaxf((aw + bb.w - rm.w) * rsqrtf(rv.w + EPSV) * gm.w + bt.w, 0.f);
    __nv_bfloat162 q0 = __floats2bfloat162_rn(o.x, o.y);
    __nv_bfloat162 q1 = __floats2bfloat162_rn(o.z, o.w);
    uint2 qo; qo.x = *(uint32_t*)&q0; qo.y = *(uint32_t*)&q1;
    *(uint2*)(g_hbf + ((unsigned)w << 7) + f) = qo;
}

// ---------------------------------------------------------------------------
// Fused segmented mean-pool (bf16 in, fp32 accumulate) + widened MLP head.
// One block (256 threads) per graph.  Deterministic.
// ---------------------------------------------------------------------------
__global__ void k_poolhead(const float* __restrict__ fc1w, const float* __restrict__ fc1b,
                           const float* __restrict__ fc2w, const float* __restrict__ fc2b,
                           float* __restrict__ out) {
    int g   = blockIdx.x;
    int tid = threadIdx.x;          // 256
    int t    = tid & 127;
    int half = tid >> 7;
    __shared__ float ssum[HDIM];
    __shared__ float ge[HDIM];
    __shared__ float p1[256];
    __shared__ float h1[64];

    int s0 = g_gstart[g];
    int s1 = g_gstart[g + 1];
    float acc = 0.f;
#pragma unroll 4
    for (int r = s0 + half; r < s1; r += 2)
        acc += __bfloat162float(g_hbf[(size_t)r * HDIM + t]);
    if (half == 1) ssum[t] = acc;
    __syncthreads();
    if (half == 0) {
        float cnt = fmaxf((float)(s1 - s0), 1.f);
        ge[t] = (acc + ssum[t]) / cnt;
    }
    __syncthreads();

    // fc1: 256 threads, output o = tid&63, quarter q = tid>>6 (32 terms each)
    {
        int o = tid & 63, q = tid >> 6;
        float a = 0.f;
#pragma unroll
        for (int i = q * 32; i < q * 32 + 32; i++) a += ge[i] * fc1w[i * 64 + o];
        p1[tid] = a;
    }
    __syncthreads();
    if (tid < 64) {
        float s = fc1b[tid] + p1[tid] + p1[64 + tid] + p1[128 + tid] + p1[192 + tid];
        h1[tid] = fmaxf(s, 0.f);
    }
    __syncthreads();
    if (tid < 10) {
        float o = fc2b[tid];
#pragma unroll
        for (int jq = 0; jq < 64; jq++) o += h1[jq] * fc2w[jq * 10 + tid];
        out[g * 10 + tid] = o;
    }
}

// ---------------------------------------------------------------------------

extern "C" void kernel_launch(void* const* d_in, const int* in_sizes, int n_in,
                              void* d_out, int out_size) {
    const float* x      = (const float*)d_in[0];
    const int*   eidx   = (const int*)  d_in[1];
    const int*   batch  = (const int*)  d_in[2];
    const float* W_in   = (const float*)d_in[3];
    const float* b_in   = (const float*)d_in[4];
    const float* Ws     = (const float*)d_in[5];
    const float* bs     = (const float*)d_in[6];
    const float* gammas = (const float*)d_in[7];
    const float* betas  = (const float*)d_in[8];
    const float* rmeans = (const float*)d_in[9];
    const float* rvars  = (const float*)d_in[10];
    const float* fc1w   = (const float*)d_in[11];
    const float* fc1b   = (const float*)d_in[12];
    const float* fc2w   = (const float*)d_in[13];
    const float* fc2b   = (const float*)d_in[14];
    float* out = (float*)d_out;

    int N = in_sizes[2];
    int E = in_sizes[1] / 2;
    int G = out_size / 10;
    const int* src = eidx;
    const int* dst = eidx + E;

    cudaFuncSetAttribute(k_gemm_tc<0>, cudaFuncAttributeMaxDynamicSharedMemorySize, GEMM_SMEM);
    cudaFuncSetAttribute(k_gemm_tc<1>, cudaFuncAttributeMaxDynamicSharedMemorySize, GEMM_SMEM);

    const int TB = 256;
    k_hist<<<(E + TB - 1) / TB, TB>>>(dst, E);
    int nb = (N + 1023) / 1024;
    k_scan1<<<nb, 1024>>>(N);
    k_scan2<<<1, 128>>>(nb);
    k_scan3<<<nb, 1024>>>(N);
    k_scatter<<<(E + TB - 1) / TB, TB>>>(src, dst, E);
    int gb = (N + TB - 1) / TB;
    int cb = (5 * HDIM * HDIM + TB - 1) / TB;
    k_misc<<<gb + cb, TB>>>(batch, N, G, gb, W_in, Ws);

    int gblk = (N + 127) / 128;
    k_gemm_tc<0><<<gblk, 256, GEMM_SMEM>>>(x, 0, b_in, N);
    for (int l = 0; l < LAYERS; l++) {
        k_gemm_tc<1><<<gblk, 256, GEMM_SMEM>>>(nullptr, (1 + l) * HDIM * HDIM, nullptr, N);
        int aggBlocks = (N * 32 + TB - 1) / TB;
        k_agg<<<aggBlocks, TB>>>(bs + l * HDIM, gammas + l * HDIM, betas + l * HDIM,
                                 rmeans + l * HDIM, rvars + l * HDIM, N, E);
    }

    k_poolhead<<<G, 256>>>(fc1w, fc1b, fc2w, fc2b, out);
}

// round 11
// speedup vs baseline: 1.2878x; 1.0366x over previous
#include <cuda_runtime.h>
#include <cuda_bf16.h>
#include <cstdint>

// ---------------------------------------------------------------------------
// BaselineGNN: 4-layer GCN inference.
//   merged setup (hist+gbound+cvtW) -> scan1 -> scan23 -> scatter ->
//   bf16 tensor-core GEMMs (split-weight hi+lo, full-K, 96KB smem, cp.async)
//   -> bf16 CSR gather (x8 body + scalar tail -- best measured form) ->
//   deterministic segmented mean-pool + widened MLP head
//   14 kernel launches total.
// ---------------------------------------------------------------------------

namespace {
constexpr int NMAX  = 100000;
constexpr int EMAX  = 1600000;
constexpr int HDIM  = 128;
constexpr int GMAX  = 256;
constexpr int LAYERS = 4;
constexpr float EPSV = 1e-5f;
constexpr int GEMM_SMEM = 3 * 128 * 128 * 2;   // 98304 B
}

__device__ __nv_bfloat16 g_hbf [NMAX * HDIM];   // h  (GEMM in / agg out / pool in)
__device__ __nv_bfloat16 g_hwbf[NMAX * HDIM];   // hw (GEMM out / agg in)
__device__ __nv_bfloat16 g_wbf_hi[5 * HDIM * HDIM];
__device__ __nv_bfloat16 g_wbf_lo[5 * HDIM * HDIM];
__device__ int   g_degc[NMAX];                  // zero at entry, re-zeroed by scan1
__device__ float g_dinv[NMAX];
__device__ int   g_off[NMAX];
__device__ int   g_cur[NMAX];
__device__ int   g_bsums[128];
__device__ int   g_csr_src[EMAX];
__device__ float g_csr_w[EMAX];
__device__ int   g_gstart[GMAX + 1];

// ---------------------------------------------------------------------------
// setup: histogram (blocks [0,eb)) + graph boundaries ([eb,eb+gb)) +
// weight hi/lo conversion (rest).  All three are independent.
// ---------------------------------------------------------------------------
__global__ void k_setup(const int* __restrict__ dst, int e, int eb,
                        const int* __restrict__ batch, int n, int G, int gb,
                        const float* __restrict__ W_in, const float* __restrict__ Ws) {
    int b = blockIdx.x;
    if (b < eb) {
        int i = b * 256 + threadIdx.x;
        if (i < e) atomicAdd(&g_degc[dst[i]], 1);
    } else if (b < eb + gb) {
        int i = (b - eb) * 256 + threadIdx.x;
        if (i >= n) return;
        int bi = batch[i];
        int bp = (i == 0) ? -1 : batch[i - 1];
        for (int g = bp + 1; g <= bi; g++) g_gstart[g] = i;
        if (i == n - 1)
            for (int g = bi + 1; g <= G; g++) g_gstart[g] = n;
    } else {
        int i = (b - eb - gb) * 256 + threadIdx.x;
        if (i >= 5 * HDIM * HDIM) return;
        float w = (i < HDIM * HDIM) ? W_in[i] : Ws[i - HDIM * HDIM];
        __nv_bfloat16 hi = __float2bfloat16_rn(w);
        g_wbf_hi[i] = hi;
        g_wbf_lo[i] = __float2bfloat16_rn(w - __bfloat162float(hi));
    }
}

// scan1: reads degc, produces dinv + block-local exclusive scan, then zeroes
// degc so the next graph replay starts from a clean histogram.
__global__ void k_scan1(int n) {
    __shared__ int tmp[1024];
    int gid = blockIdx.x * 1024 + threadIdx.x;
    int v = 0;
    if (gid < n) {
        v = g_degc[gid];
        g_degc[gid] = 0;                          // self-clean for next replay
        g_dinv[gid] = rsqrtf((float)(v + 1));
    }
    tmp[threadIdx.x] = v;
    __syncthreads();
    for (int d = 1; d < 1024; d <<= 1) {
        int t = (threadIdx.x >= d) ? tmp[threadIdx.x - d] : 0;
        __syncthreads();
        tmp[threadIdx.x] += t;
        __syncthreads();
    }
    if (gid < n) g_off[gid] = tmp[threadIdx.x] - v;   // exclusive
    if (threadIdx.x == 1023) g_bsums[blockIdx.x] = tmp[1023];
}

// scan23: each block redundantly scans the (<=128) block sums in smem to get
// its own offset, then applies it.  Removes the separate scan2 launch.
__global__ void k_scan23(int n, int nb) {
    __shared__ int s[128];
    int tid = threadIdx.x;
    if (tid < 128) s[tid] = (tid < nb) ? g_bsums[tid] : 0;
    __syncthreads();
    for (int d = 1; d < 128; d <<= 1) {
        int t = (tid >= d && tid < 128) ? s[tid - d] : 0;
        __syncthreads();
        if (tid < 128) s[tid] += t;                 // inclusive
        __syncthreads();
    }
    int boff = (blockIdx.x == 0) ? 0 : s[blockIdx.x - 1];
    int gid = blockIdx.x * 1024 + tid;
    if (gid < n) {
        int v = g_off[gid] + boff;
        g_off[gid] = v;
        g_cur[gid] = v;
    }
}

__global__ void k_scatter(const int* __restrict__ src, const int* __restrict__ dst, int e) {
    int i = blockIdx.x * blockDim.x + threadIdx.x;
    if (i < e) {
        int d = dst[i], s = src[i];
        int p = atomicAdd(&g_cur[d], 1);
        g_csr_src[p] = s;
        g_csr_w[p]   = g_dinv[s] * g_dinv[d];
    }
}

// ---------------------------------------------------------------------------
// Tensor-core GEMM: C[M,128] = A[M,128] @ (W_hi + W_lo)[128,128]
// Full K resident (96KB dynamic smem), cp.async loads, single sync.
// ---------------------------------------------------------------------------

__device__ __forceinline__ void cp_async16(uint32_t dst, const void* src) {
    asm volatile("cp.async.cg.shared.global [%0], [%1], 16;" :: "r"(dst), "l"(src));
}
__device__ __forceinline__ void cp_async_wait_all() {
    asm volatile("cp.async.commit_group;\ncp.async.wait_group 0;" ::: "memory");
}
__device__ __forceinline__ void ldsm_x4(uint32_t* r, uint32_t addr) {
    asm volatile("ldmatrix.sync.aligned.m8n8.x4.shared.b16 {%0,%1,%2,%3}, [%4];"
        : "=r"(r[0]), "=r"(r[1]), "=r"(r[2]), "=r"(r[3]) : "r"(addr));
}
__device__ __forceinline__ void ldsm_x4_t(uint32_t* r, uint32_t addr) {
    asm volatile("ldmatrix.sync.aligned.m8n8.x4.trans.shared.b16 {%0,%1,%2,%3}, [%4];"
        : "=r"(r[0]), "=r"(r[1]), "=r"(r[2]), "=r"(r[3]) : "r"(addr));
}
__device__ __forceinline__ void mma_bf16(float* c, const uint32_t* a, uint32_t b0, uint32_t b1) {
    asm volatile("mma.sync.aligned.m16n8k16.row.col.f32.bf16.bf16.f32 "
        "{%0,%1,%2,%3}, {%4,%5,%6,%7}, {%8,%9}, {%0,%1,%2,%3};"
        : "+f"(c[0]), "+f"(c[1]), "+f"(c[2]), "+f"(c[3])
        : "r"(a[0]), "r"(a[1]), "r"(a[2]), "r"(a[3]), "r"(b0), "r"(b1));
}

template <int MODE>
__global__ void __launch_bounds__(256)
k_gemm_tc(const float* __restrict__ Afp, int loff,
          const float* __restrict__ bias, int M) {
    extern __shared__ __nv_bfloat16 smem[];
    __nv_bfloat16* As  = smem;
    __nv_bfloat16* Bhs = smem + 128 * 128;
    __nv_bfloat16* Bls = smem + 2 * 128 * 128;
    const __nv_bfloat16* Whi = g_wbf_hi + loff;
    const __nv_bfloat16* Wlo = g_wbf_lo + loff;

    int tid  = threadIdx.x;
    int lane = tid & 31, wid = tid >> 5;
    int wm = wid & 3, wn = wid >> 2;
    int row0 = blockIdx.x * 128;

    uint32_t asb = (uint32_t)__cvta_generic_to_shared(As);
    uint32_t bhb = (uint32_t)__cvta_generic_to_shared(Bhs);
    uint32_t blb = (uint32_t)__cvta_generic_to_shared(Bls);

    // ---- A tile ----
#pragma unroll
    for (int i = 0; i < 8; i++) {
        int idx = tid + 256 * i;
        int r = idx >> 4, c = idx & 15;
        int gr = row0 + r;
        int sw = (c & 8) | ((c & 7) ^ (r & 7));
        if (MODE == 1) {
            uint32_t dstp = asb + (uint32_t)(r * 16 + sw) * 16;
            if (gr < M) {
                cp_async16(dstp, g_hbf + ((size_t)gr << 7) + c * 8);
            } else {
                *(uint4*)(As + (size_t)(r * 16 + sw) * 8) = make_uint4(0u, 0u, 0u, 0u);
            }
        } else {
            uint4 u = make_uint4(0u, 0u, 0u, 0u);
            if (gr < M) {
                const float4* p = (const float4*)(Afp + (size_t)gr * 128 + c * 8);
                float4 f0 = p[0], f1 = p[1];
                __nv_bfloat162 h0 = __floats2bfloat162_rn(f0.x, f0.y);
                __nv_bfloat162 h1 = __floats2bfloat162_rn(f0.z, f0.w);
                __nv_bfloat162 h2 = __floats2bfloat162_rn(f1.x, f1.y);
                __nv_bfloat162 h3 = __floats2bfloat162_rn(f1.z, f1.w);
                u.x = *(uint32_t*)&h0; u.y = *(uint32_t*)&h1;
                u.z = *(uint32_t*)&h2; u.w = *(uint32_t*)&h3;
            }
            *(uint4*)(As + (size_t)(r * 16 + sw) * 8) = u;
        }
    }
    // ---- B tiles (hi + lo) via cp.async ----
#pragma unroll
    for (int i = 0; i < 8; i++) {
        int idx = tid + 256 * i;
        int k = idx >> 4, c = idx & 15;
        int sw = (c & 8) | ((c & 7) ^ (k & 7));
        cp_async16(bhb + (uint32_t)(k * 16 + sw) * 16, Whi + (size_t)k * 128 + c * 8);
        cp_async16(blb + (uint32_t)(k * 16 + sw) * 16, Wlo + (size_t)k * 128 + c * 8);
    }
    cp_async_wait_all();
    __syncthreads();

    float acc[2][8][4];
#pragma unroll
    for (int mi = 0; mi < 2; mi++)
#pragma unroll
        for (int nj = 0; nj < 8; nj++)
#pragma unroll
            for (int q = 0; q < 4; q++) acc[mi][nj][q] = 0.f;

#pragma unroll
    for (int ks = 0; ks < 8; ks++) {
        uint32_t a[2][4];
#pragma unroll
        for (int mi = 0; mi < 2; mi++) {
            int r  = wm * 32 + mi * 16 + (lane & 15);
            int ch = ks * 2 + (lane >> 4);
            int sw = (ch & 8) | ((ch & 7) ^ (r & 7));
            ldsm_x4(a[mi], asb + (uint32_t)(r * 16 + sw) * 16);
        }
#pragma unroll
        for (int nj = 0; nj < 4; nj++) {
            int k  = ks * 16 + (lane & 15);
            int ch = wn * 8 + nj * 2 + (lane >> 4);
            int sw = (ch & 8) | ((ch & 7) ^ (k & 7));
            uint32_t bh[4], bl[4];
            ldsm_x4_t(bh, bhb + (uint32_t)(k * 16 + sw) * 16);
            ldsm_x4_t(bl, blb + (uint32_t)(k * 16 + sw) * 16);
#pragma unroll
            for (int mi = 0; mi < 2; mi++) {
                mma_bf16(acc[mi][nj * 2],     a[mi], bh[0], bh[1]);
                mma_bf16(acc[mi][nj * 2 + 1], a[mi], bh[2], bh[3]);
                mma_bf16(acc[mi][nj * 2],     a[mi], bl[0], bl[1]);
                mma_bf16(acc[mi][nj * 2 + 1], a[mi], bl[2], bl[3]);
            }
        }
    }
    int gid = lane >> 2, tig = lane & 3;
    __nv_bfloat16* Out = (MODE == 0) ? g_hbf : g_hwbf;
#pragma unroll
    for (int mi = 0; mi < 2; mi++) {
#pragma unroll
        for (int nj = 0; nj < 8; nj++) {
            int col = wn * 64 + nj * 8 + tig * 2;
            float v0 = acc[mi][nj][0], v1 = acc[mi][nj][1];
            float v2 = acc[mi][nj][2], v3 = acc[mi][nj][3];
            if (MODE == 0) {
                float b0 = bias[col], b1 = bias[col + 1];
                v0 = fmaxf(v0 + b0, 0.f); v1 = fmaxf(v1 + b1, 0.f);
                v2 = fmaxf(v2 + b0, 0.f); v3 = fmaxf(v3 + b1, 0.f);
            }
            int r0 = row0 + wm * 32 + mi * 16 + gid;
            int r1 = r0 + 8;
            if (r0 < M) {
                __nv_bfloat162 p = __floats2bfloat162_rn(v0, v1);
                *(uint32_t*)(Out + (size_t)r0 * 128 + col) = *(uint32_t*)&p;
            }
            if (r1 < M) {
                __nv_bfloat162 p = __floats2bfloat162_rn(v2, v3);
                *(uint32_t*)(Out + (size_t)r1 * 128 + col) = *(uint32_t*)&p;
            }
        }
    }
}

// ---------------------------------------------------------------------------
// bf16 CSR gather + self-loop + bias + BN + relu (fp32 accumulate).
// One warp per node; lane owns 4 features.  x8 body + scalar tail
// (best measured form -- padded/predicated variants regress).
// ---------------------------------------------------------------------------
__device__ __forceinline__ void acc_edge(const __nv_bfloat16* hw, unsigned off,
                                         float wt, float& x, float& y,
                                         float& z, float& w) {
    uint2 u = *(const uint2*)(hw + off);
    float2 a0 = __bfloat1622float2(*(__nv_bfloat162*)&u.x);
    float2 a1 = __bfloat1622float2(*(__nv_bfloat162*)&u.y);
    x += a0.x * wt; y += a0.y * wt; z += a1.x * wt; w += a1.y * wt;
}

__global__ void k_agg(const float* __restrict__ bias,
                      const float* __restrict__ gamma,
                      const float* __restrict__ beta,
                      const float* __restrict__ rmean,
                      const float* __restrict__ rvar,
                      int n, int e) {
    int w    = (blockIdx.x * blockDim.x + threadIdx.x) >> 5;
    int lane = threadIdx.x & 31;
    if (w >= n) return;
    unsigned f = (unsigned)lane * 4;
    const __nv_bfloat16* hw = g_hwbf;

    float dv = g_dinv[w];
    float ws = dv * dv;
    float ax, ay, az, aw;
    {
        uint2 us = *(const uint2*)(hw + ((unsigned)w << 7) + f);
        float2 s0 = __bfloat1622float2(*(__nv_bfloat162*)&us.x);
        float2 s1 = __bfloat1622float2(*(__nv_bfloat162*)&us.y);
        ax = s0.x * ws; ay = s0.y * ws; az = s1.x * ws; aw = s1.y * ws;
    }
    float bx = 0.f, by = 0.f, bz = 0.f, bw = 0.f;

    int j0 = g_off[w];
    int j1 = (w + 1 < n) ? g_off[w + 1] : e;
    int j = j0;
    for (; j + 8 <= j1; j += 8) {
        unsigned o0 = ((unsigned)g_csr_src[j]     << 7) + f; float w0 = g_csr_w[j];
        unsigned o1 = ((unsigned)g_csr_src[j + 1] << 7) + f; float w1 = g_csr_w[j + 1];
        unsigned o2 = ((unsigned)g_csr_src[j + 2] << 7) + f; float w2 = g_csr_w[j + 2];
        unsigned o3 = ((unsigned)g_csr_src[j + 3] << 7) + f; float w3 = g_csr_w[j + 3];
        unsigned o4 = ((unsigned)g_csr_src[j + 4] << 7) + f; float w4 = g_csr_w[j + 4];
        unsigned o5 = ((unsigned)g_csr_src[j + 5] << 7) + f; float w5 = g_csr_w[j + 5];
        unsigned o6 = ((unsigned)g_csr_src[j + 6] << 7) + f; float w6 = g_csr_w[j + 6];
        unsigned o7 = ((unsigned)g_csr_src[j + 7] << 7) + f; float w7 = g_csr_w[j + 7];
        acc_edge(hw, o0, w0, ax, ay, az, aw);
        acc_edge(hw, o1, w1, bx, by, bz, bw);
        acc_edge(hw, o2, w2, ax, ay, az, aw);
        acc_edge(hw, o3, w3, bx, by, bz, bw);
        acc_edge(hw, o4, w4, ax, ay, az, aw);
        acc_edge(hw, o5, w5, bx, by, bz, bw);
        acc_edge(hw, o6, w6, ax, ay, az, aw);
        acc_edge(hw, o7, w7, bx, by, bz, bw);
    }
    for (; j < j1; j++) {
        unsigned o = ((unsigned)g_csr_src[j] << 7) + f;
        acc_edge(hw, o, g_csr_w[j], ax, ay, az, aw);
    }
    ax += bx; ay += by; az += bz; aw += bw;

    float4 bb = *(const float4*)(bias  + f);
    float4 gm = *(const float4*)(gamma + f);
    float4 bt = *(const float4*)(beta  + f);
    float4 rm = *(const float4*)(rmean + f);
    float4 rv = *(const float4*)(rvar  + f);
    float4 o;
    o.x = fmaxf((ax + bb.x - rm.x) * rsqrtf(rv.x + EPSV) * gm.x + bt.x, 0.f);
    o.y = fmaxf((ay + bb.y - rm.y) * rsqrtf(rv.y + EPSV) * gm.y + bt.y, 0.f);
    o.z = fmaxf((az + bb.z - rm.z) * rsqrtf(rv.z + EPSV) * gm.z + bt.z, 0.f);
    o.w = fmaxf((aw + bb.w - rm.w) * rsqrtf(rv.w + EPSV) * gm.w + bt.w, 0.f);
    __nv_bfloat162 q0 = __floats2bfloat162_rn(o.x, o.y);
    __nv_bfloat162 q1 = __floats2bfloat162_rn(o.z, o.w);
    uint2 qo; qo.x = *(uint32_t*)&q0; qo.y = *(uint32_t*)&q1;
    *(uint2*)(g_hbf + ((unsigned)w << 7) + f) = qo;
}

// ---------------------------------------------------------------------------
// Fused segmented mean-pool (bf16 in, fp32 accumulate) + widened MLP head.
// ---------------------------------------------------------------------------
__global__ void k_poolhead(const float* __restrict__ fc1w, const float* __restrict__ fc1b,
                           const float* __restrict__ fc2w, const float* __restrict__ fc2b,
                           float* __restrict__ out) {
    int g   = blockIdx.x;
    int tid = threadIdx.x;          // 256
    int t    = tid & 127;
    int half = tid >> 7;
    __shared__ float ssum[HDIM];
    __shared__ float ge[HDIM];
    __shared__ float p1[256];
    __shared__ float h1[64];

    int s0 = g_gstart[g];
    int s1 = g_gstart[g + 1];
    float acc = 0.f;
#pragma unroll 4
    for (int r = s0 + half; r < s1; r += 2)
        acc += __bfloat162float(g_hbf[(size_t)r * HDIM + t]);
    if (half == 1) ssum[t] = acc;
    __syncthreads();
    if (half == 0) {
        float cnt = fmaxf((float)(s1 - s0), 1.f);
        ge[t] = (acc + ssum[t]) / cnt;
    }
    __syncthreads();

    {
        int o = tid & 63, q = tid >> 6;
        float a = 0.f;
#pragma unroll
        for (int i = q * 32; i < q * 32 + 32; i++) a += ge[i] * fc1w[i * 64 + o];
        p1[tid] = a;
    }
    __syncthreads();
    if (tid < 64) {
        float s = fc1b[tid] + p1[tid] + p1[64 + tid] + p1[128 + tid] + p1[192 + tid];
        h1[tid] = fmaxf(s, 0.f);
    }
    __syncthreads();
    if (tid < 10) {
        float o = fc2b[tid];
#pragma unroll
        for (int jq = 0; jq < 64; jq++) o += h1[jq] * fc2w[jq * 10 + tid];
        out[g * 10 + tid] = o;
    }
}

// ---------------------------------------------------------------------------

extern "C" void kernel_launch(void* const* d_in, const int* in_sizes, int n_in,
                              void* d_out, int out_size) {
    const float* x      = (const float*)d_in[0];
    const int*   eidx   = (const int*)  d_in[1];
    const int*   batch  = (const int*)  d_in[2];
    const float* W_in   = (const float*)d_in[3];
    const float* b_in   = (const float*)d_in[4];
    const float* Ws     = (const float*)d_in[5];
    const float* bs     = (const float*)d_in[6];
    const float* gammas = (const float*)d_in[7];
    const float* betas  = (const float*)d_in[8];
    const float* rmeans = (const float*)d_in[9];
    const float* rvars  = (const float*)d_in[10];
    const float* fc1w   = (const float*)d_in[11];
    const float* fc1b   = (const float*)d_in[12];
    const float* fc2w   = (const float*)d_in[13];
    const float* fc2b   = (const float*)d_in[14];
    float* out = (float*)d_out;

    int N = in_sizes[2];
    int E = in_sizes[1] / 2;
    int G = out_size / 10;
    const int* src = eidx;
    const int* dst = eidx + E;

    cudaFuncSetAttribute(k_gemm_tc<0>, cudaFuncAttributeMaxDynamicSharedMemorySize, GEMM_SMEM);
    cudaFuncSetAttribute(k_gemm_tc<1>, cudaFuncAttributeMaxDynamicSharedMemorySize, GEMM_SMEM);

    const int TB = 256;
    int eb = (E + TB - 1) / TB;
    int gb = (N + TB - 1) / TB;
    int cb = (5 * HDIM * HDIM + TB - 1) / TB;
    k_setup<<<eb + gb + cb, TB>>>(dst, E, eb, batch, N, G, gb, W_in, Ws);
    int nb = (N + 1023) / 1024;
    k_scan1<<<nb, 1024>>>(N);
    k_scan23<<<nb, 1024>>>(N, nb);
    k_scatter<<<(E + TB - 1) / TB, TB>>>(src, dst, E);

    int gblk = (N + 127) / 128;
    k_gemm_tc<0><<<gblk, 256, GEMM_SMEM>>>(x, 0, b_in, N);
    for (int l = 0; l < LAYERS; l++) {
        k_gemm_tc<1><<<gblk, 256, GEMM_SMEM>>>(nullptr, (1 + l) * HDIM * HDIM, nullptr, N);
        int aggBlocks = (N * 32 + TB - 1) / TB;
        k_agg<<<aggBlocks, TB>>>(bs + l * HDIM, gammas + l * HDIM, betas + l * HDIM,
                                 rmeans + l * HDIM, rvars + l * HDIM, N, E);
    }

    k_poolhead<<<G, 256>>>(fc1w, fc1b, fc2w, fc2b, out);
}